// round 17
// baseline (speedup 1.0000x reference)
#include <cuda_runtime.h>
#include <cuda_fp16.h>
#include <math.h>
#include <cstdint>

#define HEADS 32
#define S_LEN 2048
#define BATCH 2
#define HID   4096
#define DH    128
#define NROWS (BATCH*S_LEN)   // 4096
#define NBH   (BATCH*HEADS)   // 64

// scale * log2(e): QK logits land pre-scaled for exp2
#define QSCALE 0.12752465f

// ---------------- scratch (static __device__, no allocs) ----------------
__device__ float g_cos[S_LEN*64];
__device__ float g_sin[S_LEN*64];

__device__ __half g_hsH[(size_t)NROWS*HID];
__device__ __half g_WqH[(size_t)HID*HID];
__device__ __half g_WkH[(size_t)HID*HID];
__device__ __half g_WvH[(size_t)HID*HID];
__device__ __half g_WoH[(size_t)HID*HID];
__device__ __half g_CtxH[(size_t)NROWS*HID];
__device__ __half g_QH[(size_t)NBH*S_LEN*DH];
__device__ __half g_KH[(size_t)NBH*S_LEN*DH];
__device__ __half g_VtH[(size_t)NBH*DH*S_LEN];   // [bh][dh][s]

// ---------------- helpers ----------------
__device__ __forceinline__ uint32_t smem_u32(const void* p) {
    uint32_t a;
    asm("{ .reg .u64 t; cvta.to.shared.u64 t, %1; cvt.u32.u64 %0, t; }" : "=r"(a) : "l"(p));
    return a;
}
#define CP16(dst, src)    asm volatile("cp.async.cg.shared.global [%0], [%1], 16;" :: "r"(dst), "l"(src) : "memory")
#define CP_COMMIT()       asm volatile("cp.async.commit_group;" ::: "memory")
#define CP_WAIT(n)        asm volatile("cp.async.wait_group %0;" :: "n"(n) : "memory")

#define LDSM_X4(r0,r1,r2,r3,a) \
    asm volatile("ldmatrix.sync.aligned.m8n8.x4.shared.b16 {%0,%1,%2,%3}, [%4];" \
        : "=r"(r0),"=r"(r1),"=r"(r2),"=r"(r3) : "r"(a))

#define MMA16816(d, a, b) \
    asm volatile("mma.sync.aligned.m16n8k16.row.col.f32.f16.f16.f32 " \
        "{%0,%1,%2,%3}, {%4,%5,%6,%7}, {%8,%9}, {%0,%1,%2,%3};" \
        : "+f"((d)[0]),"+f"((d)[1]),"+f"((d)[2]),"+f"((d)[3]) \
        : "r"((a)[0]),"r"((a)[1]),"r"((a)[2]),"r"((a)[3]), "r"((b)[0]),"r"((b)[1]))

#define SWZ128(x) ((x) ^ (((x) >> 3) & 0x70))

__device__ __forceinline__ uint32_t packh(float lo, float hi) {
    uint32_t r;   // first src operand -> high half
    asm("cvt.rn.f16x2.f32 %0, %1, %2;" : "=r"(r) : "f"(hi), "f"(lo));
    return r;
}

// ---------------- fp32 -> fp16 convert (5 tensors) + rope table -----------
__global__ void conv_h5_kernel(const float* s0, __half* d0,
                               const float* s1, __half* d1,
                               const float* s2, __half* d2,
                               const float* s3, __half* d3,
                               const float* s4, __half* d4,
                               const int* __restrict__ pos_ids)
{
    if (blockIdx.y == 5) {
        int i = blockIdx.x;
        if (i >= 64) return;
        double invf = pow(10000.0, -(double)(2*i) / 128.0);
        float invff = (float)invf;
        for (int s = threadIdx.x; s < S_LEN; s += blockDim.x) {
            float pos = (float)pos_ids[s];
            float ang = pos * invff;
            float sn, cs;
            sincosf(ang, &sn, &cs);
            g_cos[(s<<6) + i] = cs;
            g_sin[(s<<6) + i] = sn;
        }
        return;
    }
    const float* src;
    __half* dst;
    switch (blockIdx.y) {
        case 0: src = s0; dst = d0; break;
        case 1: src = s1; dst = d1; break;
        case 2: src = s2; dst = d2; break;
        case 3: src = s3; dst = d3; break;
        default: src = s4; dst = d4; break;
    }
    int i = (blockIdx.x*blockDim.x + threadIdx.x) * 4;
    float4 v = *(const float4*)(src + i);
    *(__half2*)(dst + i)     = __half2{__float2half(v.x), __float2half(v.y)};
    *(__half2*)(dst + i + 2) = __half2{__float2half(v.z), __float2half(v.w)};
}

#define GT1_STAGE 32768
#define GT1_SMEM  (2*GT1_STAGE)

// ---------------- merged Q/K/V projection GEMM (z selects) ----------------
__global__ __launch_bounds__(256, 2) void gemm_qkv(const __half* __restrict__ Ah)
{
    extern __shared__ char smem[];
    const uint32_t sb = smem_u32(smem);
    const int tid = threadIdx.x, wid = tid >> 5, lid = tid & 31;
    const int bm = blockIdx.y * 128, bn = blockIdx.x * 128;
    const int wm = (wid >> 2) * 64, wn = (wid & 3) * 32;
    const int z = blockIdx.z;

    const __half* Bsel = (z == 0) ? g_WqH : (z == 1) ? g_WkH : g_WvH;

    const char* aH = (const char*)Ah + (size_t)bm * (HID*2);
    const char* bH = (const char*)Bsel + (size_t)bn * (HID*2);

    int srow[4], scol[4];
    #pragma unroll
    for (int j = 0; j < 4; j++) {
        int sidx = j*256 + tid;
        srow[j] = sidx >> 3;
        scol[j] = (sidx & 7) * 16;
    }

    auto load_chunk = [&](int stage, int chunk) {
        uint32_t st = sb + stage * GT1_STAGE;
        size_t off = (size_t)chunk * 128;
        #pragma unroll
        for (int j = 0; j < 4; j++) {
            uint32_t d = SWZ128((uint32_t)(srow[j]*128 + scol[j]));
            size_t g = (size_t)srow[j] * (HID*2) + off + scol[j];
            CP16(st +     0 + d, aH + g);
            CP16(st + 16384 + d, bH + g);
        }
    };

    float acc[4][4][4];
    #pragma unroll
    for (int i = 0; i < 4; i++)
        #pragma unroll
        for (int j = 0; j < 4; j++)
            #pragma unroll
            for (int c = 0; c < 4; c++) acc[i][j][c] = 0.f;

    const int q  = lid >> 3;
    const int r8 = lid & 7;

    load_chunk(0, 0);
    CP_COMMIT();

    const int NCHUNK = HID / 64;
    for (int chunk = 0; chunk < NCHUNK; chunk++) {
        int buf = chunk & 1;
        CP_WAIT(0);
        __syncthreads();                 // single barrier: data ready + prev compute done
        if (chunk + 1 < NCHUNK) {
            load_chunk(buf ^ 1, chunk + 1);
            CP_COMMIT();
        }

        uint32_t stA  = sb + buf * GT1_STAGE;
        uint32_t stBh = stA + 16384;

        #pragma unroll
        for (int kk = 0; kk < 4; kk++) {
            uint32_t ah[16];
            #pragma unroll
            for (int i = 0; i < 4; i++) {
                int rowA = wm + i*16 + (q & 1)*8 + r8;
                int kb   = kk*32 + (q >> 1)*16;
                uint32_t off = SWZ128((uint32_t)(rowA*128 + kb));
                LDSM_X4(ah[i*4+0], ah[i*4+1], ah[i*4+2], ah[i*4+3], stA + off);
            }
            #pragma unroll
            for (int j2 = 0; j2 < 2; j2++) {
                int rowB = wn + j2*16 + (q >> 1)*8 + r8;
                int kb   = kk*32 + (q & 1)*16;
                uint32_t off = SWZ128((uint32_t)(rowB*128 + kb));
                uint32_t bh[4];
                LDSM_X4(bh[0],bh[1],bh[2],bh[3], stBh + off);
                #pragma unroll
                for (int i = 0; i < 4; i++) {
                    MMA16816(acc[i][j2*2],   &ah[i*4], &bh[0]);
                    MMA16816(acc[i][j2*2+1], &ah[i*4], &bh[2]);
                }
            }
        }
    }
    __syncthreads();                     // all MMAs done before smem reuse

    const int gr = lid >> 2;
    const int gc = (lid & 3) * 2;

    float* tile = (float*)smem;
    #pragma unroll
    for (int i = 0; i < 4; i++) {
        #pragma unroll
        for (int half = 0; half < 2; half++) {
            int row = wm + i*16 + gr + half*8;
            int sw  = (row & 7) << 2;
            #pragma unroll
            for (int j = 0; j < 4; j++) {
                int col = wn + j*8 + gc;
                float2 v = half ? make_float2(acc[i][j][2], acc[i][j][3])
                                : make_float2(acc[i][j][0], acc[i][j][1]);
                *(float2*)&tile[row*128 + (col ^ sw)] = v;
            }
        }
    }
    __syncthreads();

    const int b  = bm >> 11;
    const int s0 = bm & (S_LEN-1);
    const int hh = blockIdx.x;
    const size_t bhBase = (size_t)(b*HEADS + hh);

    if (z < 2) {
        const float fs = (z == 0) ? QSCALE : 1.0f;
        __half* outp = ((z == 0) ? g_QH : g_KH) + bhBase * S_LEN * DH;
        #pragma unroll
        for (int p = 0; p < 32; p++) {
            int idx = p*256 + tid;
            int row = idx >> 6;
            int d   = idx & 63;
            int sw  = (row & 7) << 2;
            float x0 = tile[row*128 + (d ^ sw)];
            float x1 = tile[row*128 + ((d ^ sw) + 64)];
            int s = s0 + row;
            float cs = g_cos[(s<<6) + d];
            float sn = g_sin[(s<<6) + d];
            size_t o = (size_t)s * DH + d;
            outp[o]      = __float2half((x0*cs - x1*sn) * fs);
            outp[o + 64] = __float2half((x1*cs + x0*sn) * fs);
        }
    } else {
        __half* outp = g_VtH + bhBase * DH * S_LEN;
        #pragma unroll
        for (int p = 0; p < 64; p++) {
            int idx = p*256 + tid;
            int d    = idx >> 7;
            int sloc = idx & 127;
            int sw   = (sloc & 7) << 2;
            float v = tile[sloc*128 + (d ^ sw)];
            outp[(size_t)d * S_LEN + s0 + sloc] = __float2half(v);
        }
    }
}

// ---------------- O-projection GEMM (fp32 output) ----------------
__global__ __launch_bounds__(256, 2) void gemm_mma1(
    const __half* __restrict__ Ah, const __half* __restrict__ Bh,
    float* __restrict__ Cf)
{
    extern __shared__ char smem[];
    const uint32_t sb = smem_u32(smem);
    const int tid = threadIdx.x, wid = tid >> 5, lid = tid & 31;
    const int bm = blockIdx.y * 128, bn = blockIdx.x * 128;
    const int wm = (wid >> 2) * 64, wn = (wid & 3) * 32;

    const char* aH = (const char*)Ah + (size_t)bm * (HID*2);
    const char* bH = (const char*)Bh + (size_t)bn * (HID*2);

    int srow[4], scol[4];
    #pragma unroll
    for (int j = 0; j < 4; j++) {
        int sidx = j*256 + tid;
        srow[j] = sidx >> 3;
        scol[j] = (sidx & 7) * 16;
    }

    auto load_chunk = [&](int stage, int chunk) {
        uint32_t st = sb + stage * GT1_STAGE;
        size_t off = (size_t)chunk * 128;
        #pragma unroll
        for (int j = 0; j < 4; j++) {
            uint32_t d = SWZ128((uint32_t)(srow[j]*128 + scol[j]));
            size_t g = (size_t)srow[j] * (HID*2) + off + scol[j];
            CP16(st +     0 + d, aH + g);
            CP16(st + 16384 + d, bH + g);
        }
    };

    float acc[4][4][4];
    #pragma unroll
    for (int i = 0; i < 4; i++)
        #pragma unroll
        for (int j = 0; j < 4; j++)
            #pragma unroll
            for (int c = 0; c < 4; c++) acc[i][j][c] = 0.f;

    const int q  = lid >> 3;
    const int r8 = lid & 7;

    load_chunk(0, 0);
    CP_COMMIT();

    const int NCHUNK = HID / 64;
    for (int chunk = 0; chunk < NCHUNK; chunk++) {
        int buf = chunk & 1;
        CP_WAIT(0);
        __syncthreads();
        if (chunk + 1 < NCHUNK) {
            load_chunk(buf ^ 1, chunk + 1);
            CP_COMMIT();
        }

        uint32_t stA  = sb + buf * GT1_STAGE;
        uint32_t stBh = stA + 16384;

        #pragma unroll
        for (int kk = 0; kk < 4; kk++) {
            uint32_t ah[16];
            #pragma unroll
            for (int i = 0; i < 4; i++) {
                int rowA = wm + i*16 + (q & 1)*8 + r8;
                int kb   = kk*32 + (q >> 1)*16;
                uint32_t off = SWZ128((uint32_t)(rowA*128 + kb));
                LDSM_X4(ah[i*4+0], ah[i*4+1], ah[i*4+2], ah[i*4+3], stA + off);
            }
            #pragma unroll
            for (int j2 = 0; j2 < 2; j2++) {
                int rowB = wn + j2*16 + (q >> 1)*8 + r8;
                int kb   = kk*32 + (q & 1)*16;
                uint32_t off = SWZ128((uint32_t)(rowB*128 + kb));
                uint32_t bh[4];
                LDSM_X4(bh[0],bh[1],bh[2],bh[3], stBh + off);
                #pragma unroll
                for (int i = 0; i < 4; i++) {
                    MMA16816(acc[i][j2*2],   &ah[i*4], &bh[0]);
                    MMA16816(acc[i][j2*2+1], &ah[i*4], &bh[2]);
                }
            }
        }
    }

    const int gr = lid >> 2;
    const int gc = (lid & 3) * 2;
    #pragma unroll
    for (int i = 0; i < 4; i++) {
        #pragma unroll
        for (int half = 0; half < 2; half++) {
            int row = bm + wm + i*16 + gr + half*8;
            #pragma unroll
            for (int j = 0; j < 4; j++) {
                int col = wn + j*8 + gc;
                float2 v = half ? make_float2(acc[i][j][2], acc[i][j][3])
                                : make_float2(acc[i][j][0], acc[i][j][1]);
                *(float2*)(Cf + (size_t)row * HID + bn + col) = v;
            }
        }
    }
}

// ---------------- HMMA flash attention: 64 q-rows/CTA, 128 thr, 2 CTA/SM --
#define AT_STAGE 32768
#define AT2_SMEM (16384 + 2*AT_STAGE)

__global__ __launch_bounds__(128, 2) void attn_mma()
{
    extern __shared__ char smem[];
    const uint32_t sb = smem_u32(smem);
    const int tid = threadIdx.x, wid = tid >> 5, lid = tid & 31;
    const int qt = gridDim.x - 1 - blockIdx.x;
    const int h = blockIdx.y, b = blockIdx.z;
    const size_t bh = (size_t)b*HEADS + h;
    const int q  = lid >> 3;
    const int r8 = lid & 7;

    const char* qHb = (const char*)g_QH + (bh*S_LEN + (size_t)qt*64) * 256;
    const char* kHb = (const char*)g_KH + bh*S_LEN*256;
    const char* vHb = (const char*)g_VtH + bh*DH*(size_t)S_LEN*2;

    #pragma unroll
    for (int it = 0; it < 8; it++) {
        int e = it*128 + tid;
        int row = e >> 4, seg = e & 15;
        int panel = seg >> 3, c = seg & 7;
        uint32_t d = SWZ128((uint32_t)(row*128 + c*16));
        CP16(sb + panel*8192 + d, qHb + row*256 + seg*16);
    }

    auto load_kv = [&](int st, int kt) {
        uint32_t stb = sb + 16384 + st*AT_STAGE;
        #pragma unroll
        for (int it = 0; it < 8; it++) {
            int e = it*128 + tid;
            int row = e >> 4, seg = e & 15;
            int panel = seg >> 3, c = seg & 7;
            uint32_t d = SWZ128((uint32_t)(row*128 + c*16));
            size_t g = (size_t)(kt*64 + row)*256 + seg*16;
            CP16(stb + panel*8192 + d, kHb + g);
        }
        #pragma unroll
        for (int it = 0; it < 8; it++) {
            int e = it*128 + tid;
            int row = e >> 3, c = e & 7;
            uint32_t d = SWZ128((uint32_t)(row*128 + c*16));
            size_t g = (size_t)row*4096 + (size_t)kt*128 + c*16;
            CP16(stb + 16384 + d, vHb + g);
        }
    };

    load_kv(0, 0);
    CP_COMMIT();

    float o[16][4];
    #pragma unroll
    for (int t = 0; t < 16; t++)
        #pragma unroll
        for (int c = 0; c < 4; c++) o[t][c] = 0.f;
    float m0 = -1e30f, m1 = -1e30f, l0 = 0.f, l1 = 0.f;

    const int qrow_lo = qt*64 + wid*16;
    const int row0 = qrow_lo + (lid >> 2);
    const int col_in = (lid & 3) * 2;

    const int nkv = qt + 1;
    for (int kt = 0; kt < nkv; kt++) {
        int buf = kt & 1;
        CP_WAIT(0);
        __syncthreads();                 // single barrier per kv step
        if (kt + 1 < nkv) {
            load_kv(buf ^ 1, kt + 1);
            CP_COMMIT();
        }

        bool skip = (kt*64 > qrow_lo + 15);
        if (!skip) {
            uint32_t stb = sb + 16384 + buf*AT_STAGE;

            float sacc[8][4];
            #pragma unroll
            for (int t = 0; t < 8; t++)
                #pragma unroll
                for (int c = 0; c < 4; c++) sacc[t][c] = 0.f;

            #pragma unroll
            for (int kk = 0; kk < 8; kk++) {
                int panel = kk >> 2;
                int kb = (kk & 3)*32;
                uint32_t qh[4];
                {
                    int rowA = wid*16 + (q & 1)*8 + r8;
                    uint32_t off = SWZ128((uint32_t)(rowA*128 + kb + (q >> 1)*16));
                    LDSM_X4(qh[0],qh[1],qh[2],qh[3], sb + panel*8192 + off);
                }
                #pragma unroll
                for (int j2 = 0; j2 < 4; j2++) {
                    int rowB = j2*16 + (q >> 1)*8 + r8;
                    uint32_t off = SWZ128((uint32_t)(rowB*128 + kb + (q & 1)*16));
                    uint32_t kh[4];
                    LDSM_X4(kh[0],kh[1],kh[2],kh[3], stb + panel*8192 + off);
                    MMA16816(sacc[j2*2],   qh, &kh[0]);
                    MMA16816(sacc[j2*2+1], qh, &kh[2]);
                }
            }

            if (kt*64 + 63 > qrow_lo) {
                #pragma unroll
                for (int t = 0; t < 8; t++) {
                    int colg = kt*64 + t*8 + col_in;
                    if (colg   > row0)   sacc[t][0] = -1e30f;
                    if (colg+1 > row0)   sacc[t][1] = -1e30f;
                    if (colg   > row0+8) sacc[t][2] = -1e30f;
                    if (colg+1 > row0+8) sacc[t][3] = -1e30f;
                }
            }

            float mx0 = -1e30f, mx1 = -1e30f;
            #pragma unroll
            for (int t = 0; t < 8; t++) {
                mx0 = fmaxf(mx0, fmaxf(sacc[t][0], sacc[t][1]));
                mx1 = fmaxf(mx1, fmaxf(sacc[t][2], sacc[t][3]));
            }
            mx0 = fmaxf(mx0, __shfl_xor_sync(0xffffffffu, mx0, 1));
            mx0 = fmaxf(mx0, __shfl_xor_sync(0xffffffffu, mx0, 2));
            mx1 = fmaxf(mx1, __shfl_xor_sync(0xffffffffu, mx1, 1));
            mx1 = fmaxf(mx1, __shfl_xor_sync(0xffffffffu, mx1, 2));
            float mn0 = fmaxf(m0, mx0), mn1 = fmaxf(m1, mx1);
            float cr0 = exp2f(m0 - mn0), cr1 = exp2f(m1 - mn1);
            m0 = mn0; m1 = mn1;

            float s0 = 0.f, s1 = 0.f;
            #pragma unroll
            for (int t = 0; t < 8; t++) {
                sacc[t][0] = exp2f(sacc[t][0] - mn0);
                sacc[t][1] = exp2f(sacc[t][1] - mn0);
                sacc[t][2] = exp2f(sacc[t][2] - mn1);
                sacc[t][3] = exp2f(sacc[t][3] - mn1);
                s0 += sacc[t][0] + sacc[t][1];
                s1 += sacc[t][2] + sacc[t][3];
            }
            s0 += __shfl_xor_sync(0xffffffffu, s0, 1);
            s0 += __shfl_xor_sync(0xffffffffu, s0, 2);
            s1 += __shfl_xor_sync(0xffffffffu, s1, 1);
            s1 += __shfl_xor_sync(0xffffffffu, s1, 2);
            l0 = l0*cr0 + s0;
            l1 = l1*cr1 + s1;

            if (!__all_sync(0xffffffffu, (cr0 == 1.f) & (cr1 == 1.f))) {
                #pragma unroll
                for (int t = 0; t < 16; t++) {
                    o[t][0] *= cr0; o[t][1] *= cr0;
                    o[t][2] *= cr1; o[t][3] *= cr1;
                }
            }

            uint32_t ph[4][4];
            #pragma unroll
            for (int t = 0; t < 4; t++) {
                #pragma unroll
                for (int u = 0; u < 2; u++) {
                    ph[t][u*2+0] = packh(sacc[2*t+u][0], sacc[2*t+u][1]);
                    ph[t][u*2+1] = packh(sacc[2*t+u][2], sacc[2*t+u][3]);
                }
            }

            #pragma unroll
            for (int ks = 0; ks < 4; ks++) {
                int kb = ks*32;
                #pragma unroll
                for (int j2 = 0; j2 < 8; j2++) {
                    int rowB = j2*16 + (q >> 1)*8 + r8;
                    uint32_t off = SWZ128((uint32_t)(rowB*128 + kb + (q & 1)*16));
                    uint32_t vh[4];
                    LDSM_X4(vh[0],vh[1],vh[2],vh[3], stb + 16384 + off);
                    MMA16816(o[j2*2],   ph[ks], &vh[0]);
                    MMA16816(o[j2*2+1], ph[ks], &vh[2]);
                }
            }
        }
    }

    // ---- normalize + write Ctx as fp16 ----
    float inv0 = 1.0f / l0, inv1 = 1.0f / l1;
    size_t off0 = ((size_t)b*S_LEN + row0)     * HID + h*DH + col_in;
    size_t off1 = ((size_t)b*S_LEN + row0 + 8) * HID + h*DH + col_in;
    #pragma unroll
    for (int t = 0; t < 16; t++) {
        *(__half2*)(g_CtxH + off0 + t*8) =
            __half2{__float2half(o[t][0]*inv0), __float2half(o[t][1]*inv0)};
        *(__half2*)(g_CtxH + off1 + t*8) =
            __half2{__float2half(o[t][2]*inv1), __float2half(o[t][3]*inv1)};
    }
}

// ---------------- launch ----------------
extern "C" void kernel_launch(void* const* d_in, const int* in_sizes, int n_in,
                              void* d_out, int out_size)
{
    const float* hs = (const float*)d_in[0];
    const float* Wq = (const float*)d_in[1];
    const float* Wk = (const float*)d_in[2];
    const float* Wv = (const float*)d_in[3];
    const float* Wo = (const float*)d_in[4];
    const int* pos  = (const int*)d_in[6];
    float* out = (float*)d_out;

    __half *hsH,*WqH,*WkH,*WvH,*WoH,*CtxH;
    cudaGetSymbolAddress((void**)&hsH, g_hsH);
    cudaGetSymbolAddress((void**)&WqH, g_WqH);
    cudaGetSymbolAddress((void**)&WkH, g_WkH);
    cudaGetSymbolAddress((void**)&WvH, g_WvH);
    cudaGetSymbolAddress((void**)&WoH, g_WoH);
    cudaGetSymbolAddress((void**)&CtxH, g_CtxH);

    const int NELEM = NROWS*HID;
    const int SPLIT_BLOCKS = NELEM/4/256;

    conv_h5_kernel<<<dim3(SPLIT_BLOCKS, 6), 256>>>(hs, hsH, Wq, WqH, Wk, WkH,
                                                   Wv, WvH, Wo, WoH, pos);

    cudaFuncSetAttribute(gemm_qkv,  cudaFuncAttributeMaxDynamicSharedMemorySize, GT1_SMEM);
    cudaFuncSetAttribute(gemm_mma1, cudaFuncAttributeMaxDynamicSharedMemorySize, GT1_SMEM);

    gemm_qkv<<<dim3(HID/128, NROWS/128, 3), 256, GT1_SMEM>>>(hsH);

    cudaFuncSetAttribute(attn_mma, cudaFuncAttributeMaxDynamicSharedMemorySize, AT2_SMEM);
    attn_mma<<<dim3(S_LEN/64, HEADS, BATCH), 128, AT2_SMEM>>>();

    gemm_mma1<<<dim3(HID/128, NROWS/128), 256, GT1_SMEM>>>(CtxH, WoH, out);
}